// round 7
// baseline (speedup 1.0000x reference)
#include <cuda_runtime.h>
#include <cstdint>

#define B_    8
#define T_    4096
#define R_    1024
#define F_    64
#define I_    32
#define KTOT  96            // F_ + I_
#define NBLK  128           // scan blocks (8 rows of W_hh each)
#define NTHR  256

// ---------------- device scratch (no allocations allowed) ----------------
__device__ float    g_h[2][R_][B_];                    // ping-pong hidden state [buf][k][b]
__device__ __align__(128) unsigned g_flag[NBLK * 32];  // 1 epoch flag per CTA, 1 per 128B line

// ---------------- helpers ----------------
__device__ __forceinline__ unsigned long long pack2(float a, float b) {
    unsigned long long r;
    asm("mov.b64 %0, {%1, %2};" : "=l"(r) : "f"(a), "f"(b));
    return r;
}
__device__ __forceinline__ void fma2(unsigned long long& d, unsigned long long a, unsigned long long b) {
    asm("fma.rn.f32x2 %0, %1, %2, %0;" : "+l"(d) : "l"(a), "l"(b));
}
__device__ __forceinline__ unsigned long long add2(unsigned long long a, unsigned long long b) {
    unsigned long long r;
    asm("add.rn.f32x2 %0, %1, %2;" : "=l"(r) : "l"(a), "l"(b));
    return r;
}
__device__ __forceinline__ float2 unpack2(unsigned long long v) {
    float2 f;
    asm("mov.b64 {%0, %1}, %2;" : "=f"(f.x), "=f"(f.y) : "l"(v));
    return f;
}
__device__ __forceinline__ float tanh_fast(float x) {
    float y;
    asm("tanh.approx.f32 %0, %1;" : "=f"(y) : "f"(x));
    return y;
}

template <int HALF>
__device__ __forceinline__ void reduce_round(unsigned long long* a, int lane, int d) {
    const bool hi = (lane & d) != 0;
#pragma unroll
    for (int i = 0; i < HALF; i++) {
        unsigned long long send = hi ? a[i] : a[i + HALF];
        unsigned long long keep = hi ? a[i + HALF] : a[i];
        unsigned long long recv = __shfl_xor_sync(0xffffffffu, send, d);
        a[i] = add2(keep, recv);
    }
}

// ---------------- drive GEMM (+ folded reset): out[bt][r] = X @ [Wfb|Win]^T + b ----
#define DRIVE_SMEM ((64 + 128) * 97 * 4)

__global__ __launch_bounds__(256) void drive_kernel(
    const float* __restrict__ fb, const float* __restrict__ drv,
    const float* __restrict__ Wfb, const float* __restrict__ Win,
    const float* __restrict__ bias, float* __restrict__ out)
{
    extern __shared__ float smem[];
    float (*xs)[97]  = (float (*)[97])smem;              // [64][97]
    float (*wsh)[97] = (float (*)[97])(smem + 64 * 97);  // [128][97]

    const int r0  = blockIdx.x * 128;
    const int bt0 = blockIdx.y * 64;
    const int tid = threadIdx.x;

    // folded reset: 8 blocks (y==0) zero g_h; block (0,0) zeroes the flags
    if (blockIdx.y == 0) {
        float* p = &g_h[0][0][0] + blockIdx.x * (2 * R_ * B_ / 8);
        for (int i = tid; i < 2 * R_ * B_ / 8; i += 256) p[i] = 0.0f;
        if (blockIdx.x == 0 && tid < NBLK) g_flag[tid * 32] = 0u;
    }

    for (int idx = tid; idx < 64 * KTOT; idx += 256) {
        int row = idx / KTOT, col = idx - row * KTOT;
        float v = (col < F_) ? fb[(size_t)(bt0 + row) * F_ + col]
                             : drv[(size_t)(bt0 + row) * I_ + (col - F_)];
        xs[row][col] = v;
    }
    for (int idx = tid; idx < 128 * KTOT; idx += 256) {
        int row = idx / KTOT, col = idx - row * KTOT;
        int r = r0 + row;
        float v = (col < F_) ? Wfb[r * F_ + col] : Win[r * I_ + (col - F_)];
        wsh[row][col] = v;
    }
    __syncthreads();

    const int tx = tid & 15;
    const int ty = tid >> 4;

    float acc[4][8];
#pragma unroll
    for (int i = 0; i < 4; i++)
#pragma unroll
        for (int j = 0; j < 8; j++) acc[i][j] = 0.0f;

    for (int f = 0; f < KTOT; f++) {
        float x0 = xs[ty * 4 + 0][f];
        float x1 = xs[ty * 4 + 1][f];
        float x2 = xs[ty * 4 + 2][f];
        float x3 = xs[ty * 4 + 3][f];
        float w[8];
#pragma unroll
        for (int j = 0; j < 8; j++) w[j] = wsh[tx + 16 * j][f];
#pragma unroll
        for (int j = 0; j < 8; j++) {
            acc[0][j] = fmaf(x0, w[j], acc[0][j]);
            acc[1][j] = fmaf(x1, w[j], acc[1][j]);
            acc[2][j] = fmaf(x2, w[j], acc[2][j]);
            acc[3][j] = fmaf(x3, w[j], acc[3][j]);
        }
    }

#pragma unroll
    for (int j = 0; j < 8; j++) {
        int r = r0 + tx + 16 * j;
        float bv = bias[r];
#pragma unroll
        for (int i = 0; i < 4; i++) {
            size_t bt = (size_t)bt0 + ty * 4 + i;
            out[bt * R_ + r] = acc[i][j] + bv;
        }
    }
}

// ---------------- sequential scan: persistent, per-producer dataflow flags ----------
__global__ __launch_bounds__(NTHR, 1) void scan_kernel(
    const float* __restrict__ Whh, float* __restrict__ out)
{
    __shared__ float2 partials[2][8][32];   // double-buffered (no trailing block barrier)

    const int tid  = threadIdx.x;
    const int lane = tid & 31;
    const int warp = tid >> 5;
    const int r0   = blockIdx.x * 8;
    const int half = tid & 1;
    const int kq   = tid >> 1;

    // preload W_hh slice, duplicated pairs {w,w}
    unsigned long long wd[8][8];
#pragma unroll
    for (int i = 0; i < 8; i++) {
        int k = kq + i * 128;
#pragma unroll
        for (int j = 0; j < 8; j++) {
            float w = Whh[(size_t)(r0 + j) * R_ + k];
            wd[i][j] = pack2(w, w);
        }
    }

    const float alpha = 0.9f;
    const float onem  = 1.0f - alpha;

    size_t oi0 = 0, oi1 = 0;
    float hprev0 = 0.0f, hprev1 = 0.0f;
    float pv0 = 0.0f, pv1 = 0.0f;        // deferred out-store values
    int er = 0, eb0 = 0, eb1 = 0;
    if (warp == 0) {
        int j = lane >> 2, p = lane & 3;
        er = r0 + j; eb0 = 2 * p; eb1 = eb0 + 1;
        oi0 = ((size_t)eb0 * T_) * R_ + er;
        oi1 = ((size_t)eb1 * T_) * R_ + er;
    }

    unsigned* my_flag = &g_flag[blockIdx.x * 32];
    // warp w consumes producers {16i + 2w, 16i + 2w + 1 : i in [0,8)}; lanes 0..15
    // each poll one of those 16 flags.
    unsigned* poll_flag = &g_flag[(16 * (lane >> 1) + 2 * warp + (lane & 1)) * 32];

    for (int t = 0; t < T_; t++) {
        const int cur = t & 1, nxt = cur ^ 1;

        // ---- u(t) load + deferred out store (warp0, overlaps with wait) ----
        float u0 = 0.0f, u1 = 0.0f;
        if (warp == 0) {
            u0 = __ldcs(&out[oi0 + (size_t)t * R_]);
            u1 = __ldcs(&out[oi1 + (size_t)t * R_]);
            if (t > 0) {
                __stcg(&out[oi0 + (size_t)(t - 1) * R_], pv0);
                __stcg(&out[oi1 + (size_t)(t - 1) * R_], pv1);
            }
        }

        // ---- wait for THIS warp's 16 producers to post epoch >= t ----
        {
            const unsigned epoch = (unsigned)t;
            bool ok = (lane >= 16);
            do {
                if (!ok) {
                    unsigned f;
                    asm volatile("ld.acquire.gpu.global.u32 %0, [%1];"
                                 : "=r"(f) : "l"(poll_flag) : "memory");
                    ok = (f >= epoch);
                }
            } while (!__all_sync(0xffffffffu, ok));
        }

        // ---- load full h for this warp's chunks (L2, MLP=8) ----
        const float4* hsrc = reinterpret_cast<const float4*>(&g_h[cur][0][0]);
        float4 h4[8];
#pragma unroll
        for (int i = 0; i < 8; i++) {
            int k = kq + i * 128;
            h4[i] = __ldcg(hsrc + (k * 2 + half));
        }

        // ---- partial matvec: 8 k x 8 rows x 4 batches (f32x2) ----
        unsigned long long acc[16];
#pragma unroll
        for (int o = 0; o < 16; o++) acc[o] = 0ull;
#pragma unroll
        for (int i = 0; i < 8; i++) {
            unsigned long long h01 = pack2(h4[i].x, h4[i].y);
            unsigned long long h23 = pack2(h4[i].z, h4[i].w);
#pragma unroll
            for (int j = 0; j < 8; j++) {
                fma2(acc[j * 2 + 0], h01, wd[i][j]);
                fma2(acc[j * 2 + 1], h23, wd[i][j]);
            }
        }

        // ---- log-halving warp reduction ----
        reduce_round<8>(acc, lane, 2);
        reduce_round<4>(acc, lane, 4);
        reduce_round<2>(acc, lane, 8);
        reduce_round<1>(acc, lane, 16);

        {
            int o = (((lane >> 1) & 1) << 3) | (((lane >> 2) & 1) << 2) |
                    (((lane >> 3) & 1) << 1) | ((lane >> 4) & 1);
            int j = o >> 1, q = o & 1;
            int p = 2 * half + q;
            partials[cur][warp][j * 4 + p] = unpack2(acc[0]);
        }
        __syncthreads();                                   // (A) the only block barrier

        // ---- epilogue: warp0, tree-add + tanh, then post own flag ----
        if (warp == 0) {
            float2 p0 = partials[cur][0][lane], p1 = partials[cur][1][lane];
            float2 p2 = partials[cur][2][lane], p3 = partials[cur][3][lane];
            float2 p4 = partials[cur][4][lane], p5 = partials[cur][5][lane];
            float2 p6 = partials[cur][6][lane], p7 = partials[cur][7][lane];
            float sx = ((p0.x + p1.x) + (p2.x + p3.x)) + ((p4.x + p5.x) + (p6.x + p7.x));
            float sy = ((p0.y + p1.y) + (p2.y + p3.y)) + ((p4.y + p5.y) + (p6.y + p7.y));

            float v0 = tanh_fast(onem * hprev0 + alpha * (u0 + sx));
            float v1 = tanh_fast(onem * hprev1 + alpha * (u1 + sy));
            __stcg(&g_h[nxt][er][eb0], v0);
            __stcg(&g_h[nxt][er][eb1], v1);
            hprev0 = v0; hprev1 = v1;
            pv0 = v0; pv1 = v1;

            if (t < T_ - 1) {
                __syncwarp();   // order warp0's g_h stores before lane0's release
                if (lane == 0) {
                    asm volatile("st.release.gpu.global.u32 [%0], %1;"
                                 :: "l"(my_flag), "r"((unsigned)(t + 1)) : "memory");
                }
            }
        }
    }

    // final out store for t = T-1
    if (warp == 0) {
        __stcg(&out[oi0 + (size_t)(T_ - 1) * R_], pv0);
        __stcg(&out[oi1 + (size_t)(T_ - 1) * R_], pv1);
    }
}

// ---------------- launch ----------------
extern "C" void kernel_launch(void* const* d_in, const int* in_sizes, int n_in,
                              void* d_out, int out_size)
{
    (void)in_sizes; (void)n_in; (void)out_size;
    const float* fb   = (const float*)d_in[0];
    const float* drv  = (const float*)d_in[1];
    const float* Wfb  = (const float*)d_in[2];
    const float* Win  = (const float*)d_in[3];
    const float* Whh  = (const float*)d_in[4];
    const float* bias = (const float*)d_in[5];
    float* out = (float*)d_out;

    cudaFuncSetAttribute(drive_kernel, cudaFuncAttributeMaxDynamicSharedMemorySize, DRIVE_SMEM);

    dim3 dgrid(R_ / 128, (B_ * T_) / 64);
    drive_kernel<<<dgrid, 256, DRIVE_SMEM>>>(fb, drv, Wfb, Win, bias, out);

    scan_kernel<<<NBLK, NTHR>>>(Whh, out);
}

// round 8
// speedup vs baseline: 1.0444x; 1.0444x over previous
#include <cuda_runtime.h>
#include <cstdint>

#define B_    8
#define T_    4096
#define R_    1024
#define F_    64
#define I_    32
#define KTOT  96            // F_ + I_
#define NBLK  128           // scan blocks (8 rows of W_hh each)
#define NTHR  256

// ---------------- device scratch (no allocations allowed) ----------------
__device__ float    g_h[2][R_][B_];                    // ping-pong hidden state [buf][k][b]
__device__ __align__(128) unsigned g_flag[NBLK * 32];  // 1 epoch flag per CTA, 1 per 128B line

// ---------------- helpers ----------------
__device__ __forceinline__ unsigned long long pack2(float a, float b) {
    unsigned long long r;
    asm("mov.b64 %0, {%1, %2};" : "=l"(r) : "f"(a), "f"(b));
    return r;
}
__device__ __forceinline__ void fma2(unsigned long long& d, unsigned long long a, unsigned long long b) {
    asm("fma.rn.f32x2 %0, %1, %2, %0;" : "+l"(d) : "l"(a), "l"(b));
}
__device__ __forceinline__ unsigned long long add2(unsigned long long a, unsigned long long b) {
    unsigned long long r;
    asm("add.rn.f32x2 %0, %1, %2;" : "=l"(r) : "l"(a), "l"(b));
    return r;
}
__device__ __forceinline__ float2 unpack2(unsigned long long v) {
    float2 f;
    asm("mov.b64 {%0, %1}, %2;" : "=f"(f.x), "=f"(f.y) : "l"(v));
    return f;
}
__device__ __forceinline__ float tanh_fast(float x) {
    float y;
    asm("tanh.approx.f32 %0, %1;" : "=f"(y) : "f"(x));
    return y;
}

template <int HALF>
__device__ __forceinline__ void reduce_round(unsigned long long* a, int lane, int d) {
    const bool hi = (lane & d) != 0;
#pragma unroll
    for (int i = 0; i < HALF; i++) {
        unsigned long long send = hi ? a[i] : a[i + HALF];
        unsigned long long keep = hi ? a[i + HALF] : a[i];
        unsigned long long recv = __shfl_xor_sync(0xffffffffu, send, d);
        a[i] = add2(keep, recv);
    }
}

// ---------------- drive GEMM (+ folded reset): out[bt][r] = X @ [Wfb|Win]^T + b ----
#define DRIVE_SMEM ((64 + 128) * 97 * 4)

__global__ __launch_bounds__(256) void drive_kernel(
    const float* __restrict__ fb, const float* __restrict__ drv,
    const float* __restrict__ Wfb, const float* __restrict__ Win,
    const float* __restrict__ bias, float* __restrict__ out)
{
    extern __shared__ float smem[];
    float (*xs)[97]  = (float (*)[97])smem;              // [64][97]
    float (*wsh)[97] = (float (*)[97])(smem + 64 * 97);  // [128][97]

    const int r0  = blockIdx.x * 128;
    const int bt0 = blockIdx.y * 64;
    const int tid = threadIdx.x;

    // folded reset: 8 blocks (y==0) zero g_h; block (0,0) zeroes the flags
    if (blockIdx.y == 0) {
        float* p = &g_h[0][0][0] + blockIdx.x * (2 * R_ * B_ / 8);
        for (int i = tid; i < 2 * R_ * B_ / 8; i += 256) p[i] = 0.0f;
        if (blockIdx.x == 0 && tid < NBLK) g_flag[tid * 32] = 0u;
    }

    for (int idx = tid; idx < 64 * KTOT; idx += 256) {
        int row = idx / KTOT, col = idx - row * KTOT;
        float v = (col < F_) ? fb[(size_t)(bt0 + row) * F_ + col]
                             : drv[(size_t)(bt0 + row) * I_ + (col - F_)];
        xs[row][col] = v;
    }
    for (int idx = tid; idx < 128 * KTOT; idx += 256) {
        int row = idx / KTOT, col = idx - row * KTOT;
        int r = r0 + row;
        float v = (col < F_) ? Wfb[r * F_ + col] : Win[r * I_ + (col - F_)];
        wsh[row][col] = v;
    }
    __syncthreads();

    const int tx = tid & 15;
    const int ty = tid >> 4;

    float acc[4][8];
#pragma unroll
    for (int i = 0; i < 4; i++)
#pragma unroll
        for (int j = 0; j < 8; j++) acc[i][j] = 0.0f;

    for (int f = 0; f < KTOT; f++) {
        float x0 = xs[ty * 4 + 0][f];
        float x1 = xs[ty * 4 + 1][f];
        float x2 = xs[ty * 4 + 2][f];
        float x3 = xs[ty * 4 + 3][f];
        float w[8];
#pragma unroll
        for (int j = 0; j < 8; j++) w[j] = wsh[tx + 16 * j][f];
#pragma unroll
        for (int j = 0; j < 8; j++) {
            acc[0][j] = fmaf(x0, w[j], acc[0][j]);
            acc[1][j] = fmaf(x1, w[j], acc[1][j]);
            acc[2][j] = fmaf(x2, w[j], acc[2][j]);
            acc[3][j] = fmaf(x3, w[j], acc[3][j]);
        }
    }

#pragma unroll
    for (int j = 0; j < 8; j++) {
        int r = r0 + tx + 16 * j;
        float bv = bias[r];
#pragma unroll
        for (int i = 0; i < 4; i++) {
            size_t bt = (size_t)bt0 + ty * 4 + i;
            out[bt * R_ + r] = acc[i][j] + bv;
        }
    }
}

// ---------------- sequential scan: persistent, flat flag barrier ----------------
__global__ __launch_bounds__(NTHR, 1) void scan_kernel(
    const float* __restrict__ Whh, float* __restrict__ out)
{
    __shared__ float2 partials[7][32];     // warps 1..7 only (warp0 keeps own in regs)
    __shared__ float2 ubuf[2][32];         // u(t) staged by warp1 for warp0
    __shared__ float2 vbuf[2][32];         // v(t) staged by warp0 for warp1's out stores

    const int tid  = threadIdx.x;
    const int lane = tid & 31;
    const int warp = tid >> 5;
    const int r0   = blockIdx.x * 8;
    const int half = tid & 1;
    // per-CTA rotated k mapping: decorrelates the post-barrier L2 burst
    const int kq   = ((tid >> 1) + (blockIdx.x << 3)) & 127;

    // preload W_hh slice with the SAME rotated mapping, duplicated pairs {w,w}
    unsigned long long wd[8][8];
#pragma unroll
    for (int i = 0; i < 8; i++) {
        int k = kq + i * 128;
#pragma unroll
        for (int j = 0; j < 8; j++) {
            float w = Whh[(size_t)(r0 + j) * R_ + k];
            wd[i][j] = pack2(w, w);
        }
    }

    const float alpha = 0.9f;
    const float onem  = 1.0f - alpha;

    // lane -> (row, batch-pair) mapping shared by warp0 (epilogue) and warp1 (DRAM)
    const int ej  = lane >> 2;          // row 0..7
    const int ep  = lane & 3;           // batch-pair 0..3
    const int er  = r0 + ej;
    const int eb0 = 2 * ep, eb1 = eb0 + 1;
    const size_t oi0 = ((size_t)eb0 * T_) * R_ + er;
    const size_t oi1 = ((size_t)eb1 * T_) * R_ + er;

    float hprev0 = 0.0f, hprev1 = 0.0f;

    unsigned* my_flag   = &g_flag[blockIdx.x * 32];
    unsigned* poll_flag = (tid < NBLK) ? &g_flag[tid * 32] : nullptr;

    // prologue: warp1 stages u(0)
    if (warp == 1) {
        float a = __ldcs(&out[oi0]);
        float b = __ldcs(&out[oi1]);
        ubuf[0][lane] = make_float2(a, b);
    }
    __syncthreads();

    for (int t = 0; t < T_; t++) {
        const int cur = t & 1, nxt = cur ^ 1;

        // ---- warp1: all DRAM traffic, overlapped with everyone else's compute ----
        if (warp == 1) {
            if (t + 1 < T_) {
                float a = __ldcs(&out[oi0 + (size_t)(t + 1) * R_]);
                float b = __ldcs(&out[oi1 + (size_t)(t + 1) * R_]);
                ubuf[nxt][lane] = make_float2(a, b);
            }
            if (t > 0) {
                float2 v = vbuf[nxt][lane];    // written at step t-1 ((t-1)&1 == nxt)
                __stcg(&out[oi0 + (size_t)(t - 1) * R_], v.x);
                __stcg(&out[oi1 + (size_t)(t - 1) * R_], v.y);
            }
        }

        // ---- load full h (L2, MLP=8, rotated mapping) ----
        const float4* hsrc = reinterpret_cast<const float4*>(&g_h[cur][0][0]);
        float4 h4[8];
#pragma unroll
        for (int i = 0; i < 8; i++) {
            int k = kq + i * 128;
            h4[i] = __ldcg(hsrc + (k * 2 + half));
        }

        // ---- partial matvec: 8 k x 8 rows x 4 batches (f32x2) ----
        unsigned long long acc[16];
#pragma unroll
        for (int o = 0; o < 16; o++) acc[o] = 0ull;
#pragma unroll
        for (int i = 0; i < 8; i++) {
            unsigned long long h01 = pack2(h4[i].x, h4[i].y);
            unsigned long long h23 = pack2(h4[i].z, h4[i].w);
#pragma unroll
            for (int j = 0; j < 8; j++) {
                fma2(acc[j * 2 + 0], h01, wd[i][j]);
                fma2(acc[j * 2 + 1], h23, wd[i][j]);
            }
        }

        // ---- log-halving warp reduction ----
        reduce_round<8>(acc, lane, 2);
        reduce_round<4>(acc, lane, 4);
        reduce_round<2>(acc, lane, 8);
        reduce_round<1>(acc, lane, 16);

        // lane owns output o; warps 1..7 publish to smem, warp0 keeps in regs
        const int o = (((lane >> 1) & 1) << 3) | (((lane >> 2) & 1) << 2) |
                      (((lane >> 3) & 1) << 1) | ((lane >> 4) & 1);
        float2 own = unpack2(acc[0]);
        if (warp != 0) {
            int j = o >> 1, q = o & 1;
            int p = 2 * half + q;
            partials[warp - 1][j * 4 + p] = own;
        }
        __syncthreads();                                   // (A)

        // ---- epilogue: warp0 tree-add + tanh + g_h store + flag post ----
        if (warp == 0) {
            // warp0's own partial for THIS lane's (er, eb) slot: shuffle from the
            // lane that owns it. Owner lane index: o_own = ej*2? Own mapping:
            // lane L owns output o(L); we need output (ej, pair ep) = o = ej*2*? .
            // o encodes (j = o>>1 row, q = o&1) with p = 2*half(L)+q. Invert:
            // target output index j=ej, p=ep -> q = ep&1, need half = ep>>1,
            // o = ej*2 + q, and owner lane has half(L)=ep>>1 i.e. L&1 = ep>>1.
            // Owner lane bits: b1=o>>3,b2=(o>>2)&1,b3=(o>>1)&1,b4=o&1, L0=ep>>1.
            int oo = ej * 2 + (ep & 1);
            int src = ((oo >> 3) & 1) * 2 + ((oo >> 2) & 1) * 4 +
                      ((oo >> 1) & 1) * 8 + (oo & 1) * 16 + (ep >> 1);
            float2 w0 = make_float2(__shfl_sync(0xffffffffu, own.x, src),
                                    __shfl_sync(0xffffffffu, own.y, src));

            float2 p1 = partials[0][lane], p2 = partials[1][lane];
            float2 p3 = partials[2][lane], p4 = partials[3][lane];
            float2 p5 = partials[4][lane], p6 = partials[5][lane];
            float2 p7 = partials[6][lane];
            float sx = ((w0.x + p1.x) + (p2.x + p3.x)) + ((p4.x + p5.x) + (p6.x + p7.x));
            float sy = ((w0.y + p1.y) + (p2.y + p3.y)) + ((p4.y + p5.y) + (p6.y + p7.y));

            float2 u = ubuf[cur][lane];
            float v0 = tanh_fast(onem * hprev0 + alpha * (u.x + sx));
            float v1 = tanh_fast(onem * hprev1 + alpha * (u.y + sy));
            __stcg(&g_h[nxt][er][eb0], v0);
            __stcg(&g_h[nxt][er][eb1], v1);
            hprev0 = v0; hprev1 = v1;
            vbuf[cur][lane] = make_float2(v0, v1);

            if (t < T_ - 1) {
                __syncwarp();   // order warp0's g_h stores before lane0's release
                if (lane == 0) {
                    asm volatile("st.release.gpu.global.u32 [%0], %1;"
                                 :: "l"(my_flag), "r"((unsigned)(t + 1)) : "memory");
                }
            }
        }

        if (t < T_ - 1) {
            // ---- wait: thread i acquire-polls CTA i's flag; 128 in parallel ----
            if (tid < NBLK) {
                const unsigned epoch = (unsigned)(t + 1);
                unsigned f;
                do {
                    asm volatile("ld.acquire.gpu.global.u32 %0, [%1];"
                                 : "=r"(f) : "l"(poll_flag) : "memory");
                } while (f < epoch);
            }
            __syncthreads();                               // (C) barrier complete
        }
    }

    // final out store for t = T-1 (vbuf[(T-1)&1] written by warp0 this step)
    __syncthreads();
    if (warp == 1) {
        float2 v = vbuf[(T_ - 1) & 1][lane];
        __stcg(&out[oi0 + (size_t)(T_ - 1) * R_], v.x);
        __stcg(&out[oi1 + (size_t)(T_ - 1) * R_], v.y);
    }
}

// ---------------- launch ----------------
extern "C" void kernel_launch(void* const* d_in, const int* in_sizes, int n_in,
                              void* d_out, int out_size)
{
    (void)in_sizes; (void)n_in; (void)out_size;
    const float* fb   = (const float*)d_in[0];
    const float* drv  = (const float*)d_in[1];
    const float* Wfb  = (const float*)d_in[2];
    const float* Win  = (const float*)d_in[3];
    const float* Whh  = (const float*)d_in[4];
    const float* bias = (const float*)d_in[5];
    float* out = (float*)d_out;

    cudaFuncSetAttribute(drive_kernel, cudaFuncAttributeMaxDynamicSharedMemorySize, DRIVE_SMEM);

    dim3 dgrid(R_ / 128, (B_ * T_) / 64);
    drive_kernel<<<dgrid, 256, DRIVE_SMEM>>>(fb, drv, Wfb, Win, bias, out);

    scan_kernel<<<NBLK, NTHR>>>(Whh, out);
}

// round 9
// speedup vs baseline: 1.1055x; 1.0584x over previous
#include <cuda_runtime.h>
#include <cstdint>

#define B_    8
#define T_    4096
#define R_    1024
#define F_    64
#define I_    32
#define KTOT  96            // F_ + I_
#define NBLK  128           // scan blocks (8 rows of W_hh each)
#define NTHR  288           // 8 compute warps + 1 DMA warp

// ---------------- device scratch (no allocations allowed) ----------------
__device__ float    g_h[2][R_][B_];                    // ping-pong hidden state [buf][k][b]
__device__ __align__(128) unsigned g_flag[NBLK * 32];  // 1 epoch flag per CTA, 1 per 128B line

// ---------------- helpers ----------------
__device__ __forceinline__ unsigned long long pack2(float a, float b) {
    unsigned long long r;
    asm("mov.b64 %0, {%1, %2};" : "=l"(r) : "f"(a), "f"(b));
    return r;
}
__device__ __forceinline__ void fma2(unsigned long long& d, unsigned long long a, unsigned long long b) {
    asm("fma.rn.f32x2 %0, %1, %2, %0;" : "+l"(d) : "l"(a), "l"(b));
}
__device__ __forceinline__ unsigned long long add2(unsigned long long a, unsigned long long b) {
    unsigned long long r;
    asm("add.rn.f32x2 %0, %1, %2;" : "=l"(r) : "l"(a), "l"(b));
    return r;
}
__device__ __forceinline__ float2 unpack2(unsigned long long v) {
    float2 f;
    asm("mov.b64 {%0, %1}, %2;" : "=f"(f.x), "=f"(f.y) : "l"(v));
    return f;
}
__device__ __forceinline__ float tanh_fast(float x) {
    float y;
    asm("tanh.approx.f32 %0, %1;" : "=f"(y) : "f"(x));
    return y;
}

template <int HALF>
__device__ __forceinline__ void reduce_round(unsigned long long* a, int lane, int d) {
    const bool hi = (lane & d) != 0;
#pragma unroll
    for (int i = 0; i < HALF; i++) {
        unsigned long long send = hi ? a[i] : a[i + HALF];
        unsigned long long keep = hi ? a[i + HALF] : a[i];
        unsigned long long recv = __shfl_xor_sync(0xffffffffu, send, d);
        a[i] = add2(keep, recv);
    }
}

// ---------------- drive GEMM (+ folded reset): out[bt][r] = X @ [Wfb|Win]^T + b ----
#define DRIVE_SMEM ((64 + 128) * 97 * 4)

__global__ __launch_bounds__(256) void drive_kernel(
    const float* __restrict__ fb, const float* __restrict__ drv,
    const float* __restrict__ Wfb, const float* __restrict__ Win,
    const float* __restrict__ bias, float* __restrict__ out)
{
    extern __shared__ float smem[];
    float (*xs)[97]  = (float (*)[97])smem;              // [64][97]
    float (*wsh)[97] = (float (*)[97])(smem + 64 * 97);  // [128][97]

    const int r0  = blockIdx.x * 128;
    const int bt0 = blockIdx.y * 64;
    const int tid = threadIdx.x;

    // folded reset: 8 blocks (y==0) zero g_h; block (0,0) zeroes the flags
    if (blockIdx.y == 0) {
        float* p = &g_h[0][0][0] + blockIdx.x * (2 * R_ * B_ / 8);
        for (int i = tid; i < 2 * R_ * B_ / 8; i += 256) p[i] = 0.0f;
        if (blockIdx.x == 0 && tid < NBLK) g_flag[tid * 32] = 0u;
    }

    for (int idx = tid; idx < 64 * KTOT; idx += 256) {
        int row = idx / KTOT, col = idx - row * KTOT;
        float v = (col < F_) ? fb[(size_t)(bt0 + row) * F_ + col]
                             : drv[(size_t)(bt0 + row) * I_ + (col - F_)];
        xs[row][col] = v;
    }
    for (int idx = tid; idx < 128 * KTOT; idx += 256) {
        int row = idx / KTOT, col = idx - row * KTOT;
        int r = r0 + row;
        float v = (col < F_) ? Wfb[r * F_ + col] : Win[r * I_ + (col - F_)];
        wsh[row][col] = v;
    }
    __syncthreads();

    const int tx = tid & 15;
    const int ty = tid >> 4;

    float acc[4][8];
#pragma unroll
    for (int i = 0; i < 4; i++)
#pragma unroll
        for (int j = 0; j < 8; j++) acc[i][j] = 0.0f;

    for (int f = 0; f < KTOT; f++) {
        float x0 = xs[ty * 4 + 0][f];
        float x1 = xs[ty * 4 + 1][f];
        float x2 = xs[ty * 4 + 2][f];
        float x3 = xs[ty * 4 + 3][f];
        float w[8];
#pragma unroll
        for (int j = 0; j < 8; j++) w[j] = wsh[tx + 16 * j][f];
#pragma unroll
        for (int j = 0; j < 8; j++) {
            acc[0][j] = fmaf(x0, w[j], acc[0][j]);
            acc[1][j] = fmaf(x1, w[j], acc[1][j]);
            acc[2][j] = fmaf(x2, w[j], acc[2][j]);
            acc[3][j] = fmaf(x3, w[j], acc[3][j]);
        }
    }

#pragma unroll
    for (int j = 0; j < 8; j++) {
        int r = r0 + tx + 16 * j;
        float bv = bias[r];
#pragma unroll
        for (int i = 0; i < 4; i++) {
            size_t bt = (size_t)bt0 + ty * 4 + i;
            out[bt * R_ + r] = acc[i][j] + bv;
        }
    }
}

// ---------------- sequential scan: persistent, flat flag barrier + DMA warp ------
__global__ __launch_bounds__(NTHR, 1) void scan_kernel(
    const float* __restrict__ Whh, float* __restrict__ out)
{
    __shared__ float2 partials[8][32];   // compute warps 0..7
    __shared__ float2 ubuf[2][32];       // u(t) staged by warp8 for warp0
    __shared__ float2 vbuf[2][32];       // v(t) staged by warp0 for warp8's out stores

    const int tid  = threadIdx.x;
    const int lane = tid & 31;
    const int warp = tid >> 5;           // 0..7 compute, 8 = DMA
    const int r0   = blockIdx.x * 8;
    const int half = tid & 1;
    const int kq   = (tid >> 1) & 127;   // valid for compute warps (tid < 256)

    // preload W_hh slice (compute warps only), duplicated pairs {w,w}
    unsigned long long wd[8][8];
    if (warp < 8) {
#pragma unroll
        for (int i = 0; i < 8; i++) {
            int k = kq + i * 128;
#pragma unroll
            for (int j = 0; j < 8; j++) {
                float w = Whh[(size_t)(r0 + j) * R_ + k];
                wd[i][j] = pack2(w, w);
            }
        }
    }

    const float alpha = 0.9f;
    const float onem  = 1.0f - alpha;

    // lane -> (row, batch-pair) mapping shared by warp0 (epilogue) and warp8 (DRAM)
    const int ej  = lane >> 2;          // row 0..7
    const int ep  = lane & 3;           // batch-pair 0..3
    const int er  = r0 + ej;
    const int eb0 = 2 * ep, eb1 = eb0 + 1;
    const size_t oi0 = ((size_t)eb0 * T_) * R_ + er;
    const size_t oi1 = ((size_t)eb1 * T_) * R_ + er;

    float hprev0 = 0.0f, hprev1 = 0.0f;

    unsigned* my_flag   = &g_flag[blockIdx.x * 32];
    unsigned* poll_flag = (tid < NBLK) ? &g_flag[tid * 32] : nullptr;

    // prologue: DMA warp stages u(0)
    if (warp == 8) {
        float a = __ldcs(&out[oi0]);
        float b = __ldcs(&out[oi1]);
        ubuf[0][lane] = make_float2(a, b);
    }
    __syncthreads();

    for (int t = 0; t < T_; t++) {
        const int cur = t & 1, nxt = cur ^ 1;

        if (warp == 8) {
            // ---- DMA warp: all DRAM traffic, never on the critical path ----
            if (t + 1 < T_) {
                float a = __ldcs(&out[oi0 + (size_t)(t + 1) * R_]);
                float b = __ldcs(&out[oi1 + (size_t)(t + 1) * R_]);
                ubuf[nxt][lane] = make_float2(a, b);
            }
            if (t > 0) {
                float2 v = vbuf[nxt][lane];  // written by warp0 at step t-1
                __stcg(&out[oi0 + (size_t)(t - 1) * R_], v.x);
                __stcg(&out[oi1 + (size_t)(t - 1) * R_], v.y);
            }
        } else {
            // ---- load full h (L2, MLP=8) ----
            const float4* hsrc = reinterpret_cast<const float4*>(&g_h[cur][0][0]);
            float4 h4[8];
#pragma unroll
            for (int i = 0; i < 8; i++) {
                int k = kq + i * 128;
                h4[i] = __ldcg(hsrc + (k * 2 + half));
            }

            // ---- partial matvec: 8 k x 8 rows x 4 batches (f32x2) ----
            unsigned long long acc[16];
#pragma unroll
            for (int o = 0; o < 16; o++) acc[o] = 0ull;
#pragma unroll
            for (int i = 0; i < 8; i++) {
                unsigned long long h01 = pack2(h4[i].x, h4[i].y);
                unsigned long long h23 = pack2(h4[i].z, h4[i].w);
#pragma unroll
                for (int j = 0; j < 8; j++) {
                    fma2(acc[j * 2 + 0], h01, wd[i][j]);
                    fma2(acc[j * 2 + 1], h23, wd[i][j]);
                }
            }

            // ---- log-halving warp reduction ----
            reduce_round<8>(acc, lane, 2);
            reduce_round<4>(acc, lane, 4);
            reduce_round<2>(acc, lane, 8);
            reduce_round<1>(acc, lane, 16);

            int o = (((lane >> 1) & 1) << 3) | (((lane >> 2) & 1) << 2) |
                    (((lane >> 3) & 1) << 1) | ((lane >> 4) & 1);
            int j = o >> 1, q = o & 1;
            int p = 2 * half + q;
            partials[warp][j * 4 + p] = unpack2(acc[0]);
        }
        __syncthreads();                                   // (A)

        // ---- epilogue: warp0, tree-add + tanh, h_prev in regs ----
        if (warp == 0) {
            float2 p0 = partials[0][lane], p1 = partials[1][lane];
            float2 p2 = partials[2][lane], p3 = partials[3][lane];
            float2 p4 = partials[4][lane], p5 = partials[5][lane];
            float2 p6 = partials[6][lane], p7 = partials[7][lane];
            float sx = ((p0.x + p1.x) + (p2.x + p3.x)) + ((p4.x + p5.x) + (p6.x + p7.x));
            float sy = ((p0.y + p1.y) + (p2.y + p3.y)) + ((p4.y + p5.y) + (p6.y + p7.y));

            float2 u = ubuf[cur][lane];
            float v0 = tanh_fast(onem * hprev0 + alpha * (u.x + sx));
            float v1 = tanh_fast(onem * hprev1 + alpha * (u.y + sy));
            __stcg(&g_h[nxt][er][eb0], v0);
            __stcg(&g_h[nxt][er][eb1], v1);
            hprev0 = v0; hprev1 = v1;
            vbuf[cur][lane] = make_float2(v0, v1);

            if (t < T_ - 1) {
                __syncwarp();   // order warp0's g_h stores before lane0's release
                if (lane == 0) {
                    asm volatile("st.release.gpu.global.u32 [%0], %1;"
                                 :: "l"(my_flag), "r"((unsigned)(t + 1)) : "memory");
                }
            }
        }

        if (t < T_ - 1) {
            // ---- wait: thread i acquire-polls CTA i's flag; 128 in parallel ----
            if (tid < NBLK) {
                const unsigned epoch = (unsigned)(t + 1);
                unsigned f;
                do {
                    asm volatile("ld.acquire.gpu.global.u32 %0, [%1];"
                                 : "=r"(f) : "l"(poll_flag) : "memory");
                } while (f < epoch);
            }
            __syncthreads();                               // (C) barrier complete
        }
    }

    // final out store for t = T-1 (vbuf[(T-1)&1] written by warp0 this step)
    __syncthreads();
    if (warp == 8) {
        float2 v = vbuf[(T_ - 1) & 1][lane];
        __stcg(&out[oi0 + (size_t)(T_ - 1) * R_], v.x);
        __stcg(&out[oi1 + (size_t)(T_ - 1) * R_], v.y);
    }
}

// ---------------- launch ----------------
extern "C" void kernel_launch(void* const* d_in, const int* in_sizes, int n_in,
                              void* d_out, int out_size)
{
    (void)in_sizes; (void)n_in; (void)out_size;
    const float* fb   = (const float*)d_in[0];
    const float* drv  = (const float*)d_in[1];
    const float* Wfb  = (const float*)d_in[2];
    const float* Win  = (const float*)d_in[3];
    const float* Whh  = (const float*)d_in[4];
    const float* bias = (const float*)d_in[5];
    float* out = (float*)d_out;

    cudaFuncSetAttribute(drive_kernel, cudaFuncAttributeMaxDynamicSharedMemorySize, DRIVE_SMEM);

    dim3 dgrid(R_ / 128, (B_ * T_) / 64);
    drive_kernel<<<dgrid, 256, DRIVE_SMEM>>>(fb, drv, Wfb, Win, bias, out);

    scan_kernel<<<NBLK, NTHR>>>(Whh, out);
}